// round 4
// baseline (speedup 1.0000x reference)
#include <cuda_runtime.h>
#include <math.h>

#define NN 50000
#define NE 150000
#define HF 512
#define HIDF 64
#define NG 64

// ---------------- persistent scratch (device globals; no allocation) -------
__device__ float g_X [(size_t)NN * HF];
__device__ float g_A [(size_t)NN * HF];
__device__ float g_H1[(size_t)NN * HF];
__device__ float g_H2[(size_t)NN * HF];
__device__ float g_Z [(size_t)NN * HIDF];
__device__ float g_h0[NN];
__device__ float g_mask[NN];
__device__ float g_maskAgg[NN];
__device__ float g_invs[NN];
__device__ float g_s[NN];
__device__ float g_counts[NG];
__device__ unsigned g_bmax[NG];
__device__ unsigned g_bmin[NG];
__device__ float g_fmax[NG];
__device__ float g_fmin[NG];
__device__ double g_sum[HF];
__device__ double g_sumsq[HF];
__device__ float g_affA[HF];
__device__ float g_affB[HF];

__device__ __forceinline__ float leakyf(float v) { return v >= 0.f ? v : 0.01f * v; }

__device__ __forceinline__ unsigned fkey(float f) {
    unsigned u = __float_as_uint(f);
    return (u >> 31) ? ~u : (u | 0x80000000u);
}
__device__ __forceinline__ float fdecode(unsigned k) {
    unsigned u = (k >> 31) ? (k & 0x7FFFFFFFu) : ~k;
    return __uint_as_float(u);
}

// ---------------- small setup kernels --------------------------------------
__global__ void k_zero_small() {
    int t = blockIdx.x * blockDim.x + threadIdx.x;
    if (t < NG) {
        g_counts[t] = 0.f;
        g_bmax[t] = 0u;
        g_bmin[t] = 0xFFFFFFFFu;
    }
}

__global__ void k_init_scalars(const float* __restrict__ x, const int* __restrict__ batch) {
    int i = blockIdx.x * blockDim.x + threadIdx.x;
    if (i < NN) {
        float m = (fabsf(x[i]) > 0.f) ? 1.f : 0.f;
        g_mask[i] = m;
        g_maskAgg[i] = m;
        atomicAdd(&g_counts[batch[i]], 1.f);
    }
}

__global__ void k_invs(const int* __restrict__ batch) {
    int i = blockIdx.x * blockDim.x + threadIdx.x;
    if (i < NN) g_invs[i] = rsqrtf(g_counts[batch[i]]);
}

__global__ void k_mask_copy() {
    int i = blockIdx.x * blockDim.x + threadIdx.x;
    if (i < NN) g_maskAgg[i] = g_mask[i];
}

__global__ void k_mask_edge(const int* __restrict__ src, const int* __restrict__ dst) {
    int e = blockIdx.x * blockDim.x + threadIdx.x;
    if (e < NE) atomicAdd(&g_maskAgg[dst[e]], g_mask[src[e]]);
}

__global__ void k_mask_fin() {
    int i = blockIdx.x * blockDim.x + threadIdx.x;
    if (i < NN) g_mask[i] = (g_maskAgg[i] > 0.f) ? 1.f : 0.f;
}

// ---------------- conv1 scalar stage ---------------------------------------
__global__ void k_h0_init(const float* __restrict__ x, const float* __restrict__ eps) {
    int i = blockIdx.x * blockDim.x + threadIdx.x;
    if (i < NN) g_h0[i] = (1.f + eps[0]) * x[i];
}

__global__ void k_h0_edge(const float* __restrict__ x,
                          const int* __restrict__ src, const int* __restrict__ dst) {
    int e = blockIdx.x * blockDim.x + threadIdx.x;
    if (e < NE) atomicAdd(&g_h0[dst[e]], x[src[e]]);
}

// H1[i][c] = relu(h0[i]*w1[c] + b1[c])
__global__ void k_expand(const float* __restrict__ w1, const float* __restrict__ b1) {
    int idx = blockIdx.x * blockDim.x + threadIdx.x;
    if (idx >= NN * 128) return;
    int r = idx >> 7;
    int c = (idx & 127) << 2;
    float h = g_h0[r];
    float4 w = *(const float4*)(w1 + c);
    float4 b = *(const float4*)(b1 + c);
    float4 o;
    o.x = fmaxf(fmaf(h, w.x, b.x), 0.f);
    o.y = fmaxf(fmaf(h, w.y, b.y), 0.f);
    o.z = fmaxf(fmaf(h, w.z, b.z), 0.f);
    o.w = fmaxf(fmaf(h, w.w, b.w), 0.f);
    *(float4*)(g_H1 + (size_t)r * HF + c) = o;
}

// ---------------- aggregation (mid layers) ---------------------------------
// A = (1+eps)*X
__global__ void k_prepA(const float* __restrict__ eps, int li) {
    int idx = blockIdx.x * blockDim.x + threadIdx.x;
    if (idx >= NN * 128) return;
    int r = idx >> 7;
    int c = (idx & 127) << 2;
    float e = 1.f + __ldg(eps + li);
    float4 v = *(const float4*)(g_X + (size_t)r * HF + c);
    v.x *= e; v.y *= e; v.z *= e; v.w *= e;
    *(float4*)(g_A + (size_t)r * HF + c) = v;
}

// A[dst] += X[src] over all channels
__global__ void k_edge_scatter(const int* __restrict__ src, const int* __restrict__ dst) {
    int tid = blockIdx.x * blockDim.x + threadIdx.x;
    int e = tid >> 7;
    if (e >= NE) return;
    int c = (tid & 127) << 2;
    int s = __ldg(src + e);
    int d = __ldg(dst + e);
    float4 v = *(const float4*)(g_X + (size_t)s * HF + c);
    float* o = g_A + (size_t)d * HF + c;
    atomicAdd(o + 0, v.x);
    atomicAdd(o + 1, v.y);
    atomicAdd(o + 2, v.z);
    atomicAdd(o + 3, v.w);
}

// ---------------- SGEMM: C = act(A[MxK] @ B[KxN] + bias) --------------------
// EPI 0: relu.  EPI 1: leaky_relu then * rowmul[row].
template <int BN, int TN, int EPI>
__global__ void __launch_bounds__(256, 2) k_sgemm(
    const float* __restrict__ A, const float* __restrict__ B,
    const float* __restrict__ bias, float* __restrict__ C,
    int M, int N, int K, const float* __restrict__ rowmul)
{
    constexpr int BM = 128, BK = 8, TM = 8;
    constexpr int TX = BN / TN;  // 16
    __shared__ float As[BK][BM];
    __shared__ float Bs[BK][BN];

    const int tid = threadIdx.x;
    const int rowBase = blockIdx.y * BM;
    const int colBase = blockIdx.x * BN;
    const int tx = tid % TX;
    const int ty = tid / TX;

    float acc[TM][TN];
#pragma unroll
    for (int i = 0; i < TM; i++)
#pragma unroll
        for (int j = 0; j < TN; j++) acc[i][j] = 0.f;

    const int arow = tid >> 1;
    const int acol = (tid & 1) << 2;
    const int aRowG = rowBase + arow;
    const bool aValid = aRowG < M;
    const float* Ap = A + (size_t)aRowG * K + acol;

    for (int k0 = 0; k0 < K; k0 += BK) {
        float4 av = make_float4(0.f, 0.f, 0.f, 0.f);
        if (aValid) av = *(const float4*)(Ap + k0);
        As[acol + 0][arow] = av.x;
        As[acol + 1][arow] = av.y;
        As[acol + 2][arow] = av.z;
        As[acol + 3][arow] = av.w;
        if (BN == 128) {
            int brow = tid >> 5;
            int bcol = (tid & 31) << 2;
            float4 bv = *(const float4*)(B + (size_t)(k0 + brow) * N + colBase + bcol);
            Bs[brow][bcol + 0] = bv.x;
            Bs[brow][bcol + 1] = bv.y;
            Bs[brow][bcol + 2] = bv.z;
            Bs[brow][bcol + 3] = bv.w;
        } else {
            int brow = tid >> 5;
            int bcol = (tid & 31) << 1;
            float2 bv = *(const float2*)(B + (size_t)(k0 + brow) * N + colBase + bcol);
            Bs[brow][bcol + 0] = bv.x;
            Bs[brow][bcol + 1] = bv.y;
        }
        __syncthreads();
#pragma unroll
        for (int kk = 0; kk < BK; kk++) {
            float a[TM], b[TN];
#pragma unroll
            for (int i = 0; i < TM; i++) a[i] = As[kk][ty * TM + i];
#pragma unroll
            for (int j = 0; j < TN; j++) b[j] = Bs[kk][tx * TN + j];
#pragma unroll
            for (int i = 0; i < TM; i++)
#pragma unroll
                for (int j = 0; j < TN; j++)
                    acc[i][j] = fmaf(a[i], b[j], acc[i][j]);
        }
        __syncthreads();
    }

    float bs[TN];
#pragma unroll
    for (int j = 0; j < TN; j++) bs[j] = bias[colBase + tx * TN + j];

#pragma unroll
    for (int i = 0; i < TM; i++) {
        int row = rowBase + ty * TM + i;
        if (row < M) {
            float rm = 1.f;
            if (EPI == 1) rm = rowmul[row];
            float* Cp = C + (size_t)row * N + colBase + tx * TN;
#pragma unroll
            for (int j = 0; j < TN; j += 4) {
                float t0 = acc[i][j + 0] + bs[j + 0];
                float t1 = acc[i][j + 1] + bs[j + 1];
                float t2 = acc[i][j + 2] + bs[j + 2];
                float t3 = acc[i][j + 3] + bs[j + 3];
                float4 v;
                if (EPI == 0) {
                    v.x = fmaxf(t0, 0.f); v.y = fmaxf(t1, 0.f);
                    v.z = fmaxf(t2, 0.f); v.w = fmaxf(t3, 0.f);
                } else {
                    v.x = leakyf(t0) * rm; v.y = leakyf(t1) * rm;
                    v.z = leakyf(t2) * rm; v.w = leakyf(t3) * rm;
                }
                *(float4*)(Cp + j) = v;
            }
        }
    }
}

// ---------------- BatchNorm stats / finalize / apply -----------------------
// blockDim = 512, channel = threadIdx.x, grid-stride over rows.
__global__ void k_stats(const float* __restrict__ H) {
    int c = threadIdx.x;
    float s = 0.f, q = 0.f;
    for (int r = blockIdx.x; r < NN; r += gridDim.x) {
        float v = H[(size_t)r * HF + c];
        s += v;
        q = fmaf(v, v, q);
    }
    atomicAdd(&g_sum[c], (double)s);
    atomicAdd(&g_sumsq[c], (double)q);
}

__global__ void k_finalize(const float* __restrict__ g, const float* __restrict__ b) {
    int c = threadIdx.x;
    double mu = g_sum[c] * (1.0 / NN);
    double var = g_sumsq[c] * (1.0 / NN) - mu * mu;
    if (var < 0.0) var = 0.0;
    float inv = (float)(1.0 / sqrt(var + 1e-5));
    float gg = g[c];
    float a = gg * inv;
    g_affA[c] = a;
    g_affB[c] = fmaf(-a, (float)mu, b[c]);
    g_sum[c] = 0.0;
    g_sumsq[c] = 0.0;
}

// conv1: Y(H1) = leaky(aff(H2)) * mask*invs ; accumulate Y stats
__global__ void k_post_conv1() {
    int c = threadIdx.x;
    float a = g_affA[c], bb = g_affB[c];
    float s = 0.f, q = 0.f;
    for (int r = blockIdx.x; r < NN; r += gridDim.x) {
        float rs = g_mask[r] * g_invs[r];
        float h = g_H2[(size_t)r * HF + c];
        float y = leakyf(fmaf(a, h, bb)) * rs;
        g_H1[(size_t)r * HF + c] = y;
        s += y;
        q = fmaf(y, y, q);
    }
    atomicAdd(&g_sum[c], (double)s);
    atomicAdd(&g_sumsq[c], (double)q);
}

// mid: Y(H1) = (X + leaky(aff(H2))) * mask*invs ; accumulate Y stats
__global__ void k_post_res() {
    int c = threadIdx.x;
    float a = g_affA[c], bb = g_affB[c];
    float s = 0.f, q = 0.f;
    for (int r = blockIdx.x; r < NN; r += gridDim.x) {
        float rs = g_mask[r] * g_invs[r];
        float h = g_H2[(size_t)r * HF + c];
        float y = (g_X[(size_t)r * HF + c] + leakyf(fmaf(a, h, bb))) * rs;
        g_H1[(size_t)r * HF + c] = y;
        s += y;
        q = fmaf(y, y, q);
    }
    atomicAdd(&g_sum[c], (double)s);
    atomicAdd(&g_sumsq[c], (double)q);
}

// X = aff(Y)
__global__ void k_post2() {
    int idx = blockIdx.x * blockDim.x + threadIdx.x;
    if (idx >= NN * 128) return;
    int r = idx >> 7;
    int c = (idx & 127) << 2;
    float4 a = *(const float4*)(g_affA + c);
    float4 b = *(const float4*)(g_affB + c);
    float4 y = *(const float4*)(g_H1 + (size_t)r * HF + c);
    float4 o;
    o.x = fmaf(a.x, y.x, b.x);
    o.y = fmaf(a.y, y.y, b.y);
    o.z = fmaf(a.z, y.z, b.z);
    o.w = fmaf(a.w, y.w, b.w);
    *(float4*)(g_X + (size_t)r * HF + c) = o;
}

// ---------------- head ------------------------------------------------------
__global__ void k_lin2(const int* __restrict__ batch,
                       const float* __restrict__ w, const float* __restrict__ b) {
    int lane = threadIdx.x & 31;
    int warp = (blockIdx.x * blockDim.x + threadIdx.x) >> 5;
    int nwarps = (gridDim.x * blockDim.x) >> 5;
    float w0 = w[lane];
    float w1 = w[lane + 32];
    float bb = b[0];
    for (int node = warp; node < NN; node += nwarps) {
        const float* z = g_Z + (size_t)node * HIDF;
        float v = fmaf(z[lane], w0, z[lane + 32] * w1);
#pragma unroll
        for (int o = 16; o; o >>= 1) v += __shfl_xor_sync(0xFFFFFFFFu, v, o);
        if (lane == 0) {
            float s = leakyf(v + bb) * g_mask[node];
            g_s[node] = s;
            int gidx = batch[node];
            unsigned k = fkey(s);
            atomicMax(&g_bmax[gidx], k);
            atomicMin(&g_bmin[gidx], k);
        }
    }
}

__global__ void k_decode() {
    int t = threadIdx.x;
    if (t < NG) {
        g_fmax[t] = fdecode(g_bmax[t]);
        g_fmin[t] = fdecode(g_bmin[t]);
    }
}

__global__ void k_out(const int* __restrict__ batch, float* __restrict__ out) {
    int i = blockIdx.x * blockDim.x + threadIdx.x;
    if (i < NN) {
        int g = batch[i];
        float mn = g_fmin[g], mx = g_fmax[g];
        out[i] = (g_s[i] - mn) / (mx + 1e-6f - mn);
    }
}

// ---------------- launch ----------------------------------------------------
extern "C" void kernel_launch(void* const* d_in, const int* in_sizes, int n_in,
                              void* d_out, int out_size)
{
    (void)in_sizes; (void)n_in; (void)out_size;
    const float* x     = (const float*)d_in[0];
    const int*   ei    = (const int*)d_in[1];
    const int*   src   = ei;
    const int*   dst   = ei + NE;
    const int*   batch = (const int*)d_in[2];
    const float* c1w1  = (const float*)d_in[3];
    const float* c1b1  = (const float*)d_in[4];
    const float* c1w2  = (const float*)d_in[5];
    const float* c1b2  = (const float*)d_in[6];
    const float* c1bng = (const float*)d_in[7];
    const float* c1bnb = (const float*)d_in[8];
    const float* eps1  = (const float*)d_in[9];
    const float* bn1g  = (const float*)d_in[10];
    const float* bn1b  = (const float*)d_in[11];
    const float* cw1   = (const float*)d_in[12];
    const float* cb1   = (const float*)d_in[13];
    const float* cw2   = (const float*)d_in[14];
    const float* cb2   = (const float*)d_in[15];
    const float* cbng  = (const float*)d_in[16];
    const float* cbnb  = (const float*)d_in[17];
    const float* ceps  = (const float*)d_in[18];
    const float* bnsg  = (const float*)d_in[19];
    const float* bnsb  = (const float*)d_in[20];
    const float* l1w   = (const float*)d_in[21];
    const float* l1b   = (const float*)d_in[22];
    const float* l2w   = (const float*)d_in[23];
    const float* l2b   = (const float*)d_in[24];
    float* out = (float*)d_out;

    float *pX, *pA, *pH1, *pH2, *pZ, *pMask;
    cudaGetSymbolAddress((void**)&pX,  g_X);
    cudaGetSymbolAddress((void**)&pA,  g_A);
    cudaGetSymbolAddress((void**)&pH1, g_H1);
    cudaGetSymbolAddress((void**)&pH2, g_H2);
    cudaGetSymbolAddress((void**)&pZ,  g_Z);
    cudaGetSymbolAddress((void**)&pMask, g_mask);

    const int TPB = 256;
    const int gN  = (NN + TPB - 1) / TPB;
    const int gE  = (NE + TPB - 1) / TPB;
    const int gNv = (NN * 128 + TPB - 1) / TPB;
    const int gEv = (NE * 128 + TPB - 1) / TPB;
    dim3 gemmGrid(HF / 128, (NN + 127) / 128);
    dim3 gemmGrid64(HIDF / 64, (NN + 127) / 128);
    const int statsGrid = 296;

    // phase 0: mask, counts, invs
    k_zero_small<<<1, 64>>>();
    k_init_scalars<<<gN, TPB>>>(x, batch);
    k_mask_edge<<<gE, TPB>>>(src, dst);
    k_mask_fin<<<gN, TPB>>>();
    k_invs<<<gN, TPB>>>(batch);

    // conv1
    k_h0_init<<<gN, TPB>>>(x, eps1);
    k_h0_edge<<<gE, TPB>>>(x, src, dst);
    k_expand<<<gNv, TPB>>>(c1w1, c1b1);
    k_sgemm<128, 8, 0><<<gemmGrid, 256>>>(pH1, c1w2, c1b2, pH2, NN, HF, HF, nullptr);
    k_stats<<<statsGrid, 512>>>(pH2);
    k_finalize<<<1, 512>>>(c1bng, c1bnb);
    k_post_conv1<<<statsGrid, 512>>>();
    k_finalize<<<1, 512>>>(bn1g, bn1b);
    k_post2<<<gNv, TPB>>>();

    // mid layers
    for (int i = 0; i < 3; i++) {
        k_prepA<<<gNv, TPB>>>(ceps, i);
        k_edge_scatter<<<gEv, TPB>>>(src, dst);
        k_sgemm<128, 8, 0><<<gemmGrid, 256>>>(pA, cw1 + (size_t)i * HF * HF, cb1 + i * HF,
                                              pH1, NN, HF, HF, nullptr);
        k_sgemm<128, 8, 0><<<gemmGrid, 256>>>(pH1, cw2 + (size_t)i * HF * HF, cb2 + i * HF,
                                              pH2, NN, HF, HF, nullptr);
        k_stats<<<statsGrid, 512>>>(pH2);
        k_finalize<<<1, 512>>>(cbng + i * HF, cbnb + i * HF);
        k_mask_copy<<<gN, TPB>>>();
        k_mask_edge<<<gE, TPB>>>(src, dst);
        k_mask_fin<<<gN, TPB>>>();
        k_post_res<<<statsGrid, 512>>>();
        k_finalize<<<1, 512>>>(bnsg + i * HF, bnsb + i * HF);
        k_post2<<<gNv, TPB>>>();
    }

    // head
    k_sgemm<64, 4, 1><<<gemmGrid64, 256>>>(pX, l1w, l1b, pZ, NN, HIDF, HF, pMask);
    k_lin2<<<512, 256>>>(batch, l2w, l2b);
    k_decode<<<1, 64>>>();
    k_out<<<gN, TPB>>>(batch, out);
}

// round 5
// speedup vs baseline: 1.0005x; 1.0005x over previous
#include <cuda_runtime.h>
#include <math.h>

#define NN 50000
#define NE 150000
#define HF 512
#define HIDF 64
#define NG 64

// ---------------- persistent scratch (device globals; no allocation) -------
__device__ float g_X [(size_t)NN * HF];
__device__ float g_A [(size_t)NN * HF];
__device__ float g_H1[(size_t)NN * HF];
__device__ float g_H2[(size_t)NN * HF];
__device__ float g_Z [(size_t)NN * HIDF];
__device__ float g_h0[NN];
__device__ float g_mask[NN];
__device__ float g_maskAgg[NN];
__device__ float g_invs[NN];
__device__ float g_s[NN];
__device__ float g_counts[NG];
__device__ unsigned g_bmax[NG];
__device__ unsigned g_bmin[NG];
__device__ float g_fmax[NG];
__device__ float g_fmin[NG];
__device__ double g_sum[HF];
__device__ double g_sumsq[HF];
__device__ float g_affA[HF];
__device__ float g_affB[HF];

__device__ __forceinline__ float leakyf(float v) { return v >= 0.f ? v : 0.01f * v; }

__device__ __forceinline__ unsigned fkey(float f) {
    unsigned u = __float_as_uint(f);
    return (u >> 31) ? ~u : (u | 0x80000000u);
}
__device__ __forceinline__ float fdecode(unsigned k) {
    unsigned u = (k >> 31) ? (k & 0x7FFFFFFFu) : ~k;
    return __uint_as_float(u);
}

// ---------------- small setup kernels --------------------------------------
__global__ void k_zero_small() {
    int t = blockIdx.x * blockDim.x + threadIdx.x;
    if (t < NG) {
        g_counts[t] = 0.f;
        g_bmax[t] = 0u;
        g_bmin[t] = 0xFFFFFFFFu;
    }
}

__global__ void k_init_scalars(const float* __restrict__ x, const int* __restrict__ batch) {
    int i = blockIdx.x * blockDim.x + threadIdx.x;
    if (i < NN) {
        float m = (fabsf(x[i]) > 0.f) ? 1.f : 0.f;
        g_mask[i] = m;
        g_maskAgg[i] = m;
        atomicAdd(&g_counts[batch[i]], 1.f);
    }
}

__global__ void k_invs(const int* __restrict__ batch) {
    int i = blockIdx.x * blockDim.x + threadIdx.x;
    if (i < NN) g_invs[i] = rsqrtf(g_counts[batch[i]]);
}

__global__ void k_mask_copy() {
    int i = blockIdx.x * blockDim.x + threadIdx.x;
    if (i < NN) g_maskAgg[i] = g_mask[i];
}

__global__ void k_mask_edge(const int* __restrict__ src, const int* __restrict__ dst) {
    int e = blockIdx.x * blockDim.x + threadIdx.x;
    if (e < NE) atomicAdd(&g_maskAgg[dst[e]], g_mask[src[e]]);
}

__global__ void k_mask_fin() {
    int i = blockIdx.x * blockDim.x + threadIdx.x;
    if (i < NN) g_mask[i] = (g_maskAgg[i] > 0.f) ? 1.f : 0.f;
}

// ---------------- conv1 scalar stage ---------------------------------------
__global__ void k_h0_init(const float* __restrict__ x, const float* __restrict__ eps) {
    int i = blockIdx.x * blockDim.x + threadIdx.x;
    if (i < NN) g_h0[i] = (1.f + eps[0]) * x[i];
}

__global__ void k_h0_edge(const float* __restrict__ x,
                          const int* __restrict__ src, const int* __restrict__ dst) {
    int e = blockIdx.x * blockDim.x + threadIdx.x;
    if (e < NE) atomicAdd(&g_h0[dst[e]], x[src[e]]);
}

// H1[i][c] = relu(h0[i]*w1[c] + b1[c])
__global__ void k_expand(const float* __restrict__ w1, const float* __restrict__ b1) {
    int idx = blockIdx.x * blockDim.x + threadIdx.x;
    if (idx >= NN * 128) return;
    int r = idx >> 7;
    int c = (idx & 127) << 2;
    float h = g_h0[r];
    float4 w = *(const float4*)(w1 + c);
    float4 b = *(const float4*)(b1 + c);
    float4 o;
    o.x = fmaxf(fmaf(h, w.x, b.x), 0.f);
    o.y = fmaxf(fmaf(h, w.y, b.y), 0.f);
    o.z = fmaxf(fmaf(h, w.z, b.z), 0.f);
    o.w = fmaxf(fmaf(h, w.w, b.w), 0.f);
    *(float4*)(g_H1 + (size_t)r * HF + c) = o;
}

// ---------------- aggregation (mid layers) ---------------------------------
// A = (1+eps)*X
__global__ void k_prepA(const float* __restrict__ eps, int li) {
    int idx = blockIdx.x * blockDim.x + threadIdx.x;
    if (idx >= NN * 128) return;
    int r = idx >> 7;
    int c = (idx & 127) << 2;
    float e = 1.f + __ldg(eps + li);
    float4 v = *(const float4*)(g_X + (size_t)r * HF + c);
    v.x *= e; v.y *= e; v.z *= e; v.w *= e;
    *(float4*)(g_A + (size_t)r * HF + c) = v;
}

// A[dst] += X[src] over all channels
__global__ void k_edge_scatter(const int* __restrict__ src, const int* __restrict__ dst) {
    int tid = blockIdx.x * blockDim.x + threadIdx.x;
    int e = tid >> 7;
    if (e >= NE) return;
    int c = (tid & 127) << 2;
    int s = __ldg(src + e);
    int d = __ldg(dst + e);
    float4 v = *(const float4*)(g_X + (size_t)s * HF + c);
    float* o = g_A + (size_t)d * HF + c;
    atomicAdd(o + 0, v.x);
    atomicAdd(o + 1, v.y);
    atomicAdd(o + 2, v.z);
    atomicAdd(o + 3, v.w);
}

// ---------------- SGEMM: C = act(A[MxK] @ B[KxN] + bias) --------------------
// EPI 0: relu.  EPI 1: leaky_relu then * rowmul[row].
template <int BN, int TN, int EPI>
__global__ void __launch_bounds__(256, 2) k_sgemm(
    const float* __restrict__ A, const float* __restrict__ B,
    const float* __restrict__ bias, float* __restrict__ C,
    int M, int N, int K, const float* __restrict__ rowmul)
{
    constexpr int BM = 128, BK = 8, TM = 8;
    constexpr int TX = BN / TN;  // 16
    __shared__ float As[BK][BM];
    __shared__ float Bs[BK][BN];

    const int tid = threadIdx.x;
    const int rowBase = blockIdx.y * BM;
    const int colBase = blockIdx.x * BN;
    const int tx = tid % TX;
    const int ty = tid / TX;

    float acc[TM][TN];
#pragma unroll
    for (int i = 0; i < TM; i++)
#pragma unroll
        for (int j = 0; j < TN; j++) acc[i][j] = 0.f;

    const int arow = tid >> 1;
    const int acol = (tid & 1) << 2;
    const int aRowG = rowBase + arow;
    const bool aValid = aRowG < M;
    const float* Ap = A + (size_t)aRowG * K + acol;

    for (int k0 = 0; k0 < K; k0 += BK) {
        float4 av = make_float4(0.f, 0.f, 0.f, 0.f);
        if (aValid) av = *(const float4*)(Ap + k0);
        As[acol + 0][arow] = av.x;
        As[acol + 1][arow] = av.y;
        As[acol + 2][arow] = av.z;
        As[acol + 3][arow] = av.w;
        if (BN == 128) {
            int brow = tid >> 5;
            int bcol = (tid & 31) << 2;
            float4 bv = *(const float4*)(B + (size_t)(k0 + brow) * N + colBase + bcol);
            Bs[brow][bcol + 0] = bv.x;
            Bs[brow][bcol + 1] = bv.y;
            Bs[brow][bcol + 2] = bv.z;
            Bs[brow][bcol + 3] = bv.w;
        } else {
            int brow = tid >> 5;
            int bcol = (tid & 31) << 1;
            float2 bv = *(const float2*)(B + (size_t)(k0 + brow) * N + colBase + bcol);
            Bs[brow][bcol + 0] = bv.x;
            Bs[brow][bcol + 1] = bv.y;
        }
        __syncthreads();
#pragma unroll
        for (int kk = 0; kk < BK; kk++) {
            float a[TM], b[TN];
#pragma unroll
            for (int i = 0; i < TM; i++) a[i] = As[kk][ty * TM + i];
#pragma unroll
            for (int j = 0; j < TN; j++) b[j] = Bs[kk][tx * TN + j];
#pragma unroll
            for (int i = 0; i < TM; i++)
#pragma unroll
                for (int j = 0; j < TN; j++)
                    acc[i][j] = fmaf(a[i], b[j], acc[i][j]);
        }
        __syncthreads();
    }

    float bs[TN];
#pragma unroll
    for (int j = 0; j < TN; j++) bs[j] = bias[colBase + tx * TN + j];

#pragma unroll
    for (int i = 0; i < TM; i++) {
        int row = rowBase + ty * TM + i;
        if (row < M) {
            float rm = 1.f;
            if (EPI == 1) rm = rowmul[row];
            float* Cp = C + (size_t)row * N + colBase + tx * TN;
#pragma unroll
            for (int j = 0; j < TN; j += 4) {
                float t0 = acc[i][j + 0] + bs[j + 0];
                float t1 = acc[i][j + 1] + bs[j + 1];
                float t2 = acc[i][j + 2] + bs[j + 2];
                float t3 = acc[i][j + 3] + bs[j + 3];
                float4 v;
                if (EPI == 0) {
                    v.x = fmaxf(t0, 0.f); v.y = fmaxf(t1, 0.f);
                    v.z = fmaxf(t2, 0.f); v.w = fmaxf(t3, 0.f);
                } else {
                    v.x = leakyf(t0) * rm; v.y = leakyf(t1) * rm;
                    v.z = leakyf(t2) * rm; v.w = leakyf(t3) * rm;
                }
                *(float4*)(Cp + j) = v;
            }
        }
    }
}

// ---------------- BatchNorm stats / finalize / apply -----------------------
// blockDim = 512, channel = threadIdx.x, grid-stride over rows.
__global__ void k_stats(const float* __restrict__ H) {
    int c = threadIdx.x;
    float s = 0.f, q = 0.f;
    for (int r = blockIdx.x; r < NN; r += gridDim.x) {
        float v = H[(size_t)r * HF + c];
        s += v;
        q = fmaf(v, v, q);
    }
    atomicAdd(&g_sum[c], (double)s);
    atomicAdd(&g_sumsq[c], (double)q);
}

__global__ void k_finalize(const float* __restrict__ g, const float* __restrict__ b) {
    int c = threadIdx.x;
    double mu = g_sum[c] * (1.0 / NN);
    double var = g_sumsq[c] * (1.0 / NN) - mu * mu;
    if (var < 0.0) var = 0.0;
    float inv = (float)(1.0 / sqrt(var + 1e-5));
    float gg = g[c];
    float a = gg * inv;
    g_affA[c] = a;
    g_affB[c] = fmaf(-a, (float)mu, b[c]);
    g_sum[c] = 0.0;
    g_sumsq[c] = 0.0;
}

// conv1: Y(H1) = leaky(aff(H2)) * mask*invs ; accumulate Y stats
__global__ void k_post_conv1() {
    int c = threadIdx.x;
    float a = g_affA[c], bb = g_affB[c];
    float s = 0.f, q = 0.f;
    for (int r = blockIdx.x; r < NN; r += gridDim.x) {
        float rs = g_mask[r] * g_invs[r];
        float h = g_H2[(size_t)r * HF + c];
        float y = leakyf(fmaf(a, h, bb)) * rs;
        g_H1[(size_t)r * HF + c] = y;
        s += y;
        q = fmaf(y, y, q);
    }
    atomicAdd(&g_sum[c], (double)s);
    atomicAdd(&g_sumsq[c], (double)q);
}

// mid: Y(H1) = (X + leaky(aff(H2))) * mask*invs ; accumulate Y stats
__global__ void k_post_res() {
    int c = threadIdx.x;
    float a = g_affA[c], bb = g_affB[c];
    float s = 0.f, q = 0.f;
    for (int r = blockIdx.x; r < NN; r += gridDim.x) {
        float rs = g_mask[r] * g_invs[r];
        float h = g_H2[(size_t)r * HF + c];
        float y = (g_X[(size_t)r * HF + c] + leakyf(fmaf(a, h, bb))) * rs;
        g_H1[(size_t)r * HF + c] = y;
        s += y;
        q = fmaf(y, y, q);
    }
    atomicAdd(&g_sum[c], (double)s);
    atomicAdd(&g_sumsq[c], (double)q);
}

// X = aff(Y)
__global__ void k_post2() {
    int idx = blockIdx.x * blockDim.x + threadIdx.x;
    if (idx >= NN * 128) return;
    int r = idx >> 7;
    int c = (idx & 127) << 2;
    float4 a = *(const float4*)(g_affA + c);
    float4 b = *(const float4*)(g_affB + c);
    float4 y = *(const float4*)(g_H1 + (size_t)r * HF + c);
    float4 o;
    o.x = fmaf(a.x, y.x, b.x);
    o.y = fmaf(a.y, y.y, b.y);
    o.z = fmaf(a.z, y.z, b.z);
    o.w = fmaf(a.w, y.w, b.w);
    *(float4*)(g_X + (size_t)r * HF + c) = o;
}

// ---------------- head ------------------------------------------------------
__global__ void k_lin2(const int* __restrict__ batch,
                       const float* __restrict__ w, const float* __restrict__ b) {
    int lane = threadIdx.x & 31;
    int warp = (blockIdx.x * blockDim.x + threadIdx.x) >> 5;
    int nwarps = (gridDim.x * blockDim.x) >> 5;
    float w0 = w[lane];
    float w1 = w[lane + 32];
    float bb = b[0];
    for (int node = warp; node < NN; node += nwarps) {
        const float* z = g_Z + (size_t)node * HIDF;
        float v = fmaf(z[lane], w0, z[lane + 32] * w1);
#pragma unroll
        for (int o = 16; o; o >>= 1) v += __shfl_xor_sync(0xFFFFFFFFu, v, o);
        if (lane == 0) {
            float s = leakyf(v + bb) * g_mask[node];
            g_s[node] = s;
            int gidx = batch[node];
            unsigned k = fkey(s);
            atomicMax(&g_bmax[gidx], k);
            atomicMin(&g_bmin[gidx], k);
        }
    }
}

__global__ void k_decode() {
    int t = threadIdx.x;
    if (t < NG) {
        g_fmax[t] = fdecode(g_bmax[t]);
        g_fmin[t] = fdecode(g_bmin[t]);
    }
}

__global__ void k_out(const int* __restrict__ batch, float* __restrict__ out) {
    int i = blockIdx.x * blockDim.x + threadIdx.x;
    if (i < NN) {
        int g = batch[i];
        float mn = g_fmin[g], mx = g_fmax[g];
        out[i] = (g_s[i] - mn) / (mx + 1e-6f - mn);
    }
}

// ---------------- launch ----------------------------------------------------
extern "C" void kernel_launch(void* const* d_in, const int* in_sizes, int n_in,
                              void* d_out, int out_size)
{
    (void)in_sizes; (void)n_in; (void)out_size;
    const float* x     = (const float*)d_in[0];
    const int*   ei    = (const int*)d_in[1];
    const int*   src   = ei;
    const int*   dst   = ei + NE;
    const int*   batch = (const int*)d_in[2];
    const float* c1w1  = (const float*)d_in[3];
    const float* c1b1  = (const float*)d_in[4];
    const float* c1w2  = (const float*)d_in[5];
    const float* c1b2  = (const float*)d_in[6];
    const float* c1bng = (const float*)d_in[7];
    const float* c1bnb = (const float*)d_in[8];
    const float* eps1  = (const float*)d_in[9];
    const float* bn1g  = (const float*)d_in[10];
    const float* bn1b  = (const float*)d_in[11];
    const float* cw1   = (const float*)d_in[12];
    const float* cb1   = (const float*)d_in[13];
    const float* cw2   = (const float*)d_in[14];
    const float* cb2   = (const float*)d_in[15];
    const float* cbng  = (const float*)d_in[16];
    const float* cbnb  = (const float*)d_in[17];
    const float* ceps  = (const float*)d_in[18];
    const float* bnsg  = (const float*)d_in[19];
    const float* bnsb  = (const float*)d_in[20];
    const float* l1w   = (const float*)d_in[21];
    const float* l1b   = (const float*)d_in[22];
    const float* l2w   = (const float*)d_in[23];
    const float* l2b   = (const float*)d_in[24];
    float* out = (float*)d_out;

    float *pX, *pA, *pH1, *pH2, *pZ, *pMask;
    cudaGetSymbolAddress((void**)&pX,  g_X);
    cudaGetSymbolAddress((void**)&pA,  g_A);
    cudaGetSymbolAddress((void**)&pH1, g_H1);
    cudaGetSymbolAddress((void**)&pH2, g_H2);
    cudaGetSymbolAddress((void**)&pZ,  g_Z);
    cudaGetSymbolAddress((void**)&pMask, g_mask);

    const int TPB = 256;
    const int gN  = (NN + TPB - 1) / TPB;
    const int gE  = (NE + TPB - 1) / TPB;
    const int gNv = (NN * 128 + TPB - 1) / TPB;
    const int gEv = (NE * 128 + TPB - 1) / TPB;
    dim3 gemmGrid(HF / 128, (NN + 127) / 128);
    dim3 gemmGrid64(HIDF / 64, (NN + 127) / 128);
    const int statsGrid = 296;

    // phase 0: mask, counts, invs
    k_zero_small<<<1, 64>>>();
    k_init_scalars<<<gN, TPB>>>(x, batch);
    k_mask_edge<<<gE, TPB>>>(src, dst);
    k_mask_fin<<<gN, TPB>>>();
    k_invs<<<gN, TPB>>>(batch);

    // conv1
    k_h0_init<<<gN, TPB>>>(x, eps1);
    k_h0_edge<<<gE, TPB>>>(x, src, dst);
    k_expand<<<gNv, TPB>>>(c1w1, c1b1);
    k_sgemm<128, 8, 0><<<gemmGrid, 256>>>(pH1, c1w2, c1b2, pH2, NN, HF, HF, nullptr);
    k_stats<<<statsGrid, 512>>>(pH2);
    k_finalize<<<1, 512>>>(c1bng, c1bnb);
    k_post_conv1<<<statsGrid, 512>>>();
    k_finalize<<<1, 512>>>(bn1g, bn1b);
    k_post2<<<gNv, TPB>>>();

    // mid layers
    for (int i = 0; i < 3; i++) {
        k_prepA<<<gNv, TPB>>>(ceps, i);
        k_edge_scatter<<<gEv, TPB>>>(src, dst);
        k_sgemm<128, 8, 0><<<gemmGrid, 256>>>(pA, cw1 + (size_t)i * HF * HF, cb1 + i * HF,
                                              pH1, NN, HF, HF, nullptr);
        k_sgemm<128, 8, 0><<<gemmGrid, 256>>>(pH1, cw2 + (size_t)i * HF * HF, cb2 + i * HF,
                                              pH2, NN, HF, HF, nullptr);
        k_stats<<<statsGrid, 512>>>(pH2);
        k_finalize<<<1, 512>>>(cbng + i * HF, cbnb + i * HF);
        k_mask_copy<<<gN, TPB>>>();
        k_mask_edge<<<gE, TPB>>>(src, dst);
        k_mask_fin<<<gN, TPB>>>();
        k_post_res<<<statsGrid, 512>>>();
        k_finalize<<<1, 512>>>(bnsg + i * HF, bnsb + i * HF);
        k_post2<<<gNv, TPB>>>();
    }

    // head
    k_sgemm<64, 4, 1><<<gemmGrid64, 256>>>(pX, l1w, l1b, pZ, NN, HIDF, HF, pMask);
    k_lin2<<<512, 256>>>(batch, l2w, l2b);
    k_decode<<<1, 64>>>();
    k_out<<<gN, TPB>>>(batch, out);
}

// round 6
// speedup vs baseline: 1.0037x; 1.0032x over previous
#include <cuda_runtime.h>
#include <math.h>

#define NN 50000
#define NE 150000
#define HF 512
#define HIDF 64
#define NG 64

// ---------------- persistent scratch (device globals; no allocation) -------
__device__ float g_X [(size_t)NN * HF];
__device__ float g_A [(size_t)NN * HF];
__device__ float g_H1[(size_t)NN * HF];
__device__ float g_H2[(size_t)NN * HF];
__device__ float g_Z [(size_t)NN * HIDF];
__device__ float g_h0[NN];
__device__ float g_mask[NN];
__device__ float g_maskAgg[NN];
__device__ float g_invs[NN];
__device__ float g_s[NN];
__device__ float g_counts[NG];
__device__ unsigned g_bmax[NG];
__device__ unsigned g_bmin[NG];
__device__ float g_fmax[NG];
__device__ float g_fmin[NG];
__device__ double g_sum[HF];
__device__ double g_sumsq[HF];
__device__ float g_affA[HF];
__device__ float g_affB[HF];

__device__ __forceinline__ float leakyf(float v) { return v >= 0.f ? v : 0.01f * v; }

__device__ __forceinline__ unsigned fkey(float f) {
    unsigned u = __float_as_uint(f);
    return (u >> 31) ? ~u : (u | 0x80000000u);
}
__device__ __forceinline__ float fdecode(unsigned k) {
    unsigned u = (k >> 31) ? (k & 0x7FFFFFFFu) : ~k;
    return __uint_as_float(u);
}

// ---------------- small setup kernels --------------------------------------
__global__ void k_zero_small() {
    int t = blockIdx.x * blockDim.x + threadIdx.x;
    if (t < NG) {
        g_counts[t] = 0.f;
        g_bmax[t] = 0u;
        g_bmin[t] = 0xFFFFFFFFu;
    }
}

__global__ void k_init_scalars(const float* __restrict__ x, const int* __restrict__ batch) {
    int i = blockIdx.x * blockDim.x + threadIdx.x;
    if (i < NN) {
        float m = (fabsf(x[i]) > 0.f) ? 1.f : 0.f;
        g_mask[i] = m;
        g_maskAgg[i] = m;
        atomicAdd(&g_counts[batch[i]], 1.f);
    }
}

__global__ void k_invs(const int* __restrict__ batch) {
    int i = blockIdx.x * blockDim.x + threadIdx.x;
    if (i < NN) g_invs[i] = rsqrtf(g_counts[batch[i]]);
}

__global__ void k_mask_copy() {
    int i = blockIdx.x * blockDim.x + threadIdx.x;
    if (i < NN) g_maskAgg[i] = g_mask[i];
}

__global__ void k_mask_edge(const int* __restrict__ src, const int* __restrict__ dst) {
    int e = blockIdx.x * blockDim.x + threadIdx.x;
    if (e < NE) atomicAdd(&g_maskAgg[dst[e]], g_mask[src[e]]);
}

__global__ void k_mask_fin() {
    int i = blockIdx.x * blockDim.x + threadIdx.x;
    if (i < NN) g_mask[i] = (g_maskAgg[i] > 0.f) ? 1.f : 0.f;
}

// ---------------- conv1 scalar stage ---------------------------------------
__global__ void k_h0_init(const float* __restrict__ x, const float* __restrict__ eps) {
    int i = blockIdx.x * blockDim.x + threadIdx.x;
    if (i < NN) g_h0[i] = (1.f + eps[0]) * x[i];
}

__global__ void k_h0_edge(const float* __restrict__ x,
                          const int* __restrict__ src, const int* __restrict__ dst) {
    int e = blockIdx.x * blockDim.x + threadIdx.x;
    if (e < NE) atomicAdd(&g_h0[dst[e]], x[src[e]]);
}

// H1[i][c] = relu(h0[i]*w1[c] + b1[c])
__global__ void k_expand(const float* __restrict__ w1, const float* __restrict__ b1) {
    int idx = blockIdx.x * blockDim.x + threadIdx.x;
    if (idx >= NN * 128) return;
    int r = idx >> 7;
    int c = (idx & 127) << 2;
    float h = g_h0[r];
    float4 w = *(const float4*)(w1 + c);
    float4 b = *(const float4*)(b1 + c);
    float4 o;
    o.x = fmaxf(fmaf(h, w.x, b.x), 0.f);
    o.y = fmaxf(fmaf(h, w.y, b.y), 0.f);
    o.z = fmaxf(fmaf(h, w.z, b.z), 0.f);
    o.w = fmaxf(fmaf(h, w.w, b.w), 0.f);
    *(float4*)(g_H1 + (size_t)r * HF + c) = o;
}

// ---------------- aggregation (mid layers) ---------------------------------
// A = (1+eps)*X
__global__ void k_prepA(const float* __restrict__ eps, int li) {
    int idx = blockIdx.x * blockDim.x + threadIdx.x;
    if (idx >= NN * 128) return;
    int r = idx >> 7;
    int c = (idx & 127) << 2;
    float e = 1.f + __ldg(eps + li);
    float4 v = *(const float4*)(g_X + (size_t)r * HF + c);
    v.x *= e; v.y *= e; v.z *= e; v.w *= e;
    *(float4*)(g_A + (size_t)r * HF + c) = v;
}

// A[dst] += X[src] over all channels
__global__ void k_edge_scatter(const int* __restrict__ src, const int* __restrict__ dst) {
    int tid = blockIdx.x * blockDim.x + threadIdx.x;
    int e = tid >> 7;
    if (e >= NE) return;
    int c = (tid & 127) << 2;
    int s = __ldg(src + e);
    int d = __ldg(dst + e);
    float4 v = *(const float4*)(g_X + (size_t)s * HF + c);
    float* o = g_A + (size_t)d * HF + c;
    atomicAdd(o + 0, v.x);
    atomicAdd(o + 1, v.y);
    atomicAdd(o + 2, v.z);
    atomicAdd(o + 3, v.w);
}

// ---------------- SGEMM: C = act(A[MxK] @ B[KxN] + bias) --------------------
// EPI 0: relu.  EPI 1: leaky_relu then * rowmul[row].
template <int BN, int TN, int EPI>
__global__ void __launch_bounds__(256, 2) k_sgemm(
    const float* __restrict__ A, const float* __restrict__ B,
    const float* __restrict__ bias, float* __restrict__ C,
    int M, int N, int K, const float* __restrict__ rowmul)
{
    constexpr int BM = 128, BK = 8, TM = 8;
    constexpr int TX = BN / TN;  // 16
    __shared__ float As[BK][BM];
    __shared__ float Bs[BK][BN];

    const int tid = threadIdx.x;
    const int rowBase = blockIdx.y * BM;
    const int colBase = blockIdx.x * BN;
    const int tx = tid % TX;
    const int ty = tid / TX;

    float acc[TM][TN];
#pragma unroll
    for (int i = 0; i < TM; i++)
#pragma unroll
        for (int j = 0; j < TN; j++) acc[i][j] = 0.f;

    const int arow = tid >> 1;
    const int acol = (tid & 1) << 2;
    const int aRowG = rowBase + arow;
    const bool aValid = aRowG < M;
    const float* Ap = A + (size_t)aRowG * K + acol;

    for (int k0 = 0; k0 < K; k0 += BK) {
        float4 av = make_float4(0.f, 0.f, 0.f, 0.f);
        if (aValid) av = *(const float4*)(Ap + k0);
        As[acol + 0][arow] = av.x;
        As[acol + 1][arow] = av.y;
        As[acol + 2][arow] = av.z;
        As[acol + 3][arow] = av.w;
        if (BN == 128) {
            int brow = tid >> 5;
            int bcol = (tid & 31) << 2;
            float4 bv = *(const float4*)(B + (size_t)(k0 + brow) * N + colBase + bcol);
            Bs[brow][bcol + 0] = bv.x;
            Bs[brow][bcol + 1] = bv.y;
            Bs[brow][bcol + 2] = bv.z;
            Bs[brow][bcol + 3] = bv.w;
        } else {
            int brow = tid >> 5;
            int bcol = (tid & 31) << 1;
            float2 bv = *(const float2*)(B + (size_t)(k0 + brow) * N + colBase + bcol);
            Bs[brow][bcol + 0] = bv.x;
            Bs[brow][bcol + 1] = bv.y;
        }
        __syncthreads();
#pragma unroll
        for (int kk = 0; kk < BK; kk++) {
            float a[TM], b[TN];
#pragma unroll
            for (int i = 0; i < TM; i++) a[i] = As[kk][ty * TM + i];
#pragma unroll
            for (int j = 0; j < TN; j++) b[j] = Bs[kk][tx * TN + j];
#pragma unroll
            for (int i = 0; i < TM; i++)
#pragma unroll
                for (int j = 0; j < TN; j++)
                    acc[i][j] = fmaf(a[i], b[j], acc[i][j]);
        }
        __syncthreads();
    }

    float bs[TN];
#pragma unroll
    for (int j = 0; j < TN; j++) bs[j] = bias[colBase + tx * TN + j];

#pragma unroll
    for (int i = 0; i < TM; i++) {
        int row = rowBase + ty * TM + i;
        if (row < M) {
            float rm = 1.f;
            if (EPI == 1) rm = rowmul[row];
            float* Cp = C + (size_t)row * N + colBase + tx * TN;
#pragma unroll
            for (int j = 0; j < TN; j += 4) {
                float t0 = acc[i][j + 0] + bs[j + 0];
                float t1 = acc[i][j + 1] + bs[j + 1];
                float t2 = acc[i][j + 2] + bs[j + 2];
                float t3 = acc[i][j + 3] + bs[j + 3];
                float4 v;
                if (EPI == 0) {
                    v.x = fmaxf(t0, 0.f); v.y = fmaxf(t1, 0.f);
                    v.z = fmaxf(t2, 0.f); v.w = fmaxf(t3, 0.f);
                } else {
                    v.x = leakyf(t0) * rm; v.y = leakyf(t1) * rm;
                    v.z = leakyf(t2) * rm; v.w = leakyf(t3) * rm;
                }
                *(float4*)(Cp + j) = v;
            }
        }
    }
}

// ---------------- BatchNorm stats / finalize / apply -----------------------
// blockDim = 512, channel = threadIdx.x, grid-stride over rows.
__global__ void k_stats(const float* __restrict__ H) {
    int c = threadIdx.x;
    float s = 0.f, q = 0.f;
    for (int r = blockIdx.x; r < NN; r += gridDim.x) {
        float v = H[(size_t)r * HF + c];
        s += v;
        q = fmaf(v, v, q);
    }
    atomicAdd(&g_sum[c], (double)s);
    atomicAdd(&g_sumsq[c], (double)q);
}

__global__ void k_finalize(const float* __restrict__ g, const float* __restrict__ b) {
    int c = threadIdx.x;
    double mu = g_sum[c] * (1.0 / NN);
    double var = g_sumsq[c] * (1.0 / NN) - mu * mu;
    if (var < 0.0) var = 0.0;
    float inv = (float)(1.0 / sqrt(var + 1e-5));
    float gg = g[c];
    float a = gg * inv;
    g_affA[c] = a;
    g_affB[c] = fmaf(-a, (float)mu, b[c]);
    g_sum[c] = 0.0;
    g_sumsq[c] = 0.0;
}

// conv1: Y(H1) = leaky(aff(H2)) * mask*invs ; accumulate Y stats
__global__ void k_post_conv1() {
    int c = threadIdx.x;
    float a = g_affA[c], bb = g_affB[c];
    float s = 0.f, q = 0.f;
    for (int r = blockIdx.x; r < NN; r += gridDim.x) {
        float rs = g_mask[r] * g_invs[r];
        float h = g_H2[(size_t)r * HF + c];
        float y = leakyf(fmaf(a, h, bb)) * rs;
        g_H1[(size_t)r * HF + c] = y;
        s += y;
        q = fmaf(y, y, q);
    }
    atomicAdd(&g_sum[c], (double)s);
    atomicAdd(&g_sumsq[c], (double)q);
}

// mid: Y(H1) = (X + leaky(aff(H2))) * mask*invs ; accumulate Y stats
__global__ void k_post_res() {
    int c = threadIdx.x;
    float a = g_affA[c], bb = g_affB[c];
    float s = 0.f, q = 0.f;
    for (int r = blockIdx.x; r < NN; r += gridDim.x) {
        float rs = g_mask[r] * g_invs[r];
        float h = g_H2[(size_t)r * HF + c];
        float y = (g_X[(size_t)r * HF + c] + leakyf(fmaf(a, h, bb))) * rs;
        g_H1[(size_t)r * HF + c] = y;
        s += y;
        q = fmaf(y, y, q);
    }
    atomicAdd(&g_sum[c], (double)s);
    atomicAdd(&g_sumsq[c], (double)q);
}

// X = aff(Y)
__global__ void k_post2() {
    int idx = blockIdx.x * blockDim.x + threadIdx.x;
    if (idx >= NN * 128) return;
    int r = idx >> 7;
    int c = (idx & 127) << 2;
    float4 a = *(const float4*)(g_affA + c);
    float4 b = *(const float4*)(g_affB + c);
    float4 y = *(const float4*)(g_H1 + (size_t)r * HF + c);
    float4 o;
    o.x = fmaf(a.x, y.x, b.x);
    o.y = fmaf(a.y, y.y, b.y);
    o.z = fmaf(a.z, y.z, b.z);
    o.w = fmaf(a.w, y.w, b.w);
    *(float4*)(g_X + (size_t)r * HF + c) = o;
}

// ---------------- head ------------------------------------------------------
__global__ void k_lin2(const int* __restrict__ batch,
                       const float* __restrict__ w, const float* __restrict__ b) {
    int lane = threadIdx.x & 31;
    int warp = (blockIdx.x * blockDim.x + threadIdx.x) >> 5;
    int nwarps = (gridDim.x * blockDim.x) >> 5;
    float w0 = w[lane];
    float w1 = w[lane + 32];
    float bb = b[0];
    for (int node = warp; node < NN; node += nwarps) {
        const float* z = g_Z + (size_t)node * HIDF;
        float v = fmaf(z[lane], w0, z[lane + 32] * w1);
#pragma unroll
        for (int o = 16; o; o >>= 1) v += __shfl_xor_sync(0xFFFFFFFFu, v, o);
        if (lane == 0) {
            float s = leakyf(v + bb) * g_mask[node];
            g_s[node] = s;
            int gidx = batch[node];
            unsigned k = fkey(s);
            atomicMax(&g_bmax[gidx], k);
            atomicMin(&g_bmin[gidx], k);
        }
    }
}

__global__ void k_decode() {
    int t = threadIdx.x;
    if (t < NG) {
        g_fmax[t] = fdecode(g_bmax[t]);
        g_fmin[t] = fdecode(g_bmin[t]);
    }
}

__global__ void k_out(const int* __restrict__ batch, float* __restrict__ out) {
    int i = blockIdx.x * blockDim.x + threadIdx.x;
    if (i < NN) {
        int g = batch[i];
        float mn = g_fmin[g], mx = g_fmax[g];
        out[i] = (g_s[i] - mn) / (mx + 1e-6f - mn);
    }
}

// ---------------- launch ----------------------------------------------------
extern "C" void kernel_launch(void* const* d_in, const int* in_sizes, int n_in,
                              void* d_out, int out_size)
{
    (void)in_sizes; (void)n_in; (void)out_size;
    const float* x     = (const float*)d_in[0];
    const int*   ei    = (const int*)d_in[1];
    const int*   src   = ei;
    const int*   dst   = ei + NE;
    const int*   batch = (const int*)d_in[2];
    const float* c1w1  = (const float*)d_in[3];
    const float* c1b1  = (const float*)d_in[4];
    const float* c1w2  = (const float*)d_in[5];
    const float* c1b2  = (const float*)d_in[6];
    const float* c1bng = (const float*)d_in[7];
    const float* c1bnb = (const float*)d_in[8];
    const float* eps1  = (const float*)d_in[9];
    const float* bn1g  = (const float*)d_in[10];
    const float* bn1b  = (const float*)d_in[11];
    const float* cw1   = (const float*)d_in[12];
    const float* cb1   = (const float*)d_in[13];
    const float* cw2   = (const float*)d_in[14];
    const float* cb2   = (const float*)d_in[15];
    const float* cbng  = (const float*)d_in[16];
    const float* cbnb  = (const float*)d_in[17];
    const float* ceps  = (const float*)d_in[18];
    const float* bnsg  = (const float*)d_in[19];
    const float* bnsb  = (const float*)d_in[20];
    const float* l1w   = (const float*)d_in[21];
    const float* l1b   = (const float*)d_in[22];
    const float* l2w   = (const float*)d_in[23];
    const float* l2b   = (const float*)d_in[24];
    float* out = (float*)d_out;

    float *pX, *pA, *pH1, *pH2, *pZ, *pMask;
    cudaGetSymbolAddress((void**)&pX,  g_X);
    cudaGetSymbolAddress((void**)&pA,  g_A);
    cudaGetSymbolAddress((void**)&pH1, g_H1);
    cudaGetSymbolAddress((void**)&pH2, g_H2);
    cudaGetSymbolAddress((void**)&pZ,  g_Z);
    cudaGetSymbolAddress((void**)&pMask, g_mask);

    const int TPB = 256;
    const int gN  = (NN + TPB - 1) / TPB;
    const int gE  = (NE + TPB - 1) / TPB;
    const int gNv = (NN * 128 + TPB - 1) / TPB;
    const int gEv = (NE * 128 + TPB - 1) / TPB;
    dim3 gemmGrid(HF / 128, (NN + 127) / 128);
    dim3 gemmGrid64(HIDF / 64, (NN + 127) / 128);
    const int statsGrid = 296;

    // phase 0: mask, counts, invs
    k_zero_small<<<1, 64>>>();
    k_init_scalars<<<gN, TPB>>>(x, batch);
    k_mask_edge<<<gE, TPB>>>(src, dst);
    k_mask_fin<<<gN, TPB>>>();
    k_invs<<<gN, TPB>>>(batch);

    // conv1
    k_h0_init<<<gN, TPB>>>(x, eps1);
    k_h0_edge<<<gE, TPB>>>(x, src, dst);
    k_expand<<<gNv, TPB>>>(c1w1, c1b1);
    k_sgemm<128, 8, 0><<<gemmGrid, 256>>>(pH1, c1w2, c1b2, pH2, NN, HF, HF, nullptr);
    k_stats<<<statsGrid, 512>>>(pH2);
    k_finalize<<<1, 512>>>(c1bng, c1bnb);
    k_post_conv1<<<statsGrid, 512>>>();
    k_finalize<<<1, 512>>>(bn1g, bn1b);
    k_post2<<<gNv, TPB>>>();

    // mid layers
    for (int i = 0; i < 3; i++) {
        k_prepA<<<gNv, TPB>>>(ceps, i);
        k_edge_scatter<<<gEv, TPB>>>(src, dst);
        k_sgemm<128, 8, 0><<<gemmGrid, 256>>>(pA, cw1 + (size_t)i * HF * HF, cb1 + i * HF,
                                              pH1, NN, HF, HF, nullptr);
        k_sgemm<128, 8, 0><<<gemmGrid, 256>>>(pH1, cw2 + (size_t)i * HF * HF, cb2 + i * HF,
                                              pH2, NN, HF, HF, nullptr);
        k_stats<<<statsGrid, 512>>>(pH2);
        k_finalize<<<1, 512>>>(cbng + i * HF, cbnb + i * HF);
        k_mask_copy<<<gN, TPB>>>();
        k_mask_edge<<<gE, TPB>>>(src, dst);
        k_mask_fin<<<gN, TPB>>>();
        k_post_res<<<statsGrid, 512>>>();
        k_finalize<<<1, 512>>>(bnsg + i * HF, bnsb + i * HF);
        k_post2<<<gNv, TPB>>>();
    }

    // head
    k_sgemm<64, 4, 1><<<gemmGrid64, 256>>>(pX, l1w, l1b, pZ, NN, HIDF, HF, pMask);
    k_lin2<<<512, 256>>>(batch, l2w, l2b);
    k_decode<<<1, 64>>>();
    k_out<<<gN, TPB>>>(batch, out);
}